// round 12
// baseline (speedup 1.0000x reference)
#include <cuda_runtime.h>
#include <cuda_fp16.h>
#include <cstdint>

#define C_    80
#define H_    32
#define W_    88
#define HW_   (H_ * W_)          // 2816
#define NXg   128
#define NYg   128
#define NZg   16
#define NPTS  (NXg * NYg * NZg)  // 262144 points per batch
#define TPB   256
#define PPT   2                  // z-adjacent points per thread (STG.64 stores)
#define NCH8  (C_ / 8)           // 10 chunks of 8 fp16 channels (16 B)

// (B, H*W, C) channel-last fp16 copy of the feature map. 900 KB total.
__device__ __half g_imgH[2 * HW_ * C_];

// ---------------------------------------------------------------------------
// Pass 1: (B, C, HW) f32 -> (B, HW, C) fp16 tiled transpose (L2-resident)
// ---------------------------------------------------------------------------
__global__ void fvt_transpose(const float* __restrict__ img)
{
    __shared__ float tile[32][33];
    const int b   = blockIdx.z;
    const int hw0 = blockIdx.x * 32;
    const int c0  = blockIdx.y * 32;
    const int tx  = threadIdx.x;      // 0..31
    const int ty  = threadIdx.y;      // 0..7

    #pragma unroll
    for (int i = 0; i < 4; i++) {
        const int c  = c0 + ty + i * 8;
        const int hw = hw0 + tx;
        if (c < C_ && hw < HW_)
            tile[ty + i * 8][tx] = img[((size_t)b * C_ + c) * HW_ + hw];
    }
    __syncthreads();
    #pragma unroll
    for (int i = 0; i < 4; i++) {
        const int hw = hw0 + ty + i * 8;
        const int c  = c0 + tx;
        if (hw < HW_ && c < C_)
            g_imgH[((size_t)b * HW_ + hw) * C_ + c] =
                __float2half_rn(tile[tx][ty + i * 8]);
    }
}

// ---------------------------------------------------------------------------
// Pass 2: 2 z-adjacent points per thread. fp16 channel-last gathers
// (8 ch per LDG.128), f32 interpolation, STG.64 streamed stores.
// ---------------------------------------------------------------------------
__global__ __launch_bounds__(TPB, 5) void fvt_kernel(
    const float* __restrict__ intrin,  // (B, 1, 4, 4)
    const float* __restrict__ extrin,  // (B, 1, 4, 4)
    const float* __restrict__ bda,     // (B, 4, 4)
    float* __restrict__ out)           // (B, C, NX, NY, NZ)
{
    __shared__ float s_bda[16];
    __shared__ float s_proj[12];

    const int b = blockIdx.y;

    if (threadIdx.x < 16) s_bda[threadIdx.x] = bda[b * 16 + threadIdx.x];
    if (threadIdx.x < 12) {
        // proj[i][j] = sum_k (intrin[i][k] * scale_i) * extrin[k][j]
        const int i = threadIdx.x >> 2;
        const int j = threadIdx.x & 3;
        const float sc = (i < 2) ? 0.125f : 1.0f;
        const float* IN = intrin + b * 16;
        const float* EX = extrin + b * 16;
        float acc = 0.0f;
        #pragma unroll
        for (int k = 0; k < 3; k++)
            acc += (IN[i * 4 + k] * sc) * EX[k * 4 + j];
        s_proj[threadIdx.x] = acc;
    }
    __syncthreads();

    const int n0  = (blockIdx.x * TPB + threadIdx.x) * PPT;
    const int iz0 = n0 & (NZg - 1);         // PPT=2 divides 16: column-local
    const int t   = n0 >> 4;
    const int iy  = t & (NYg - 1);
    const int ix  = t >> 7;

    // match jnp: bound[0] + arange*step  (mul then add, no FMA contraction)
    const float px = __fadd_rn(__fmul_rn((float)ix, 0.8f), -51.2f);
    const float py = __fadd_rn(__fmul_rn((float)iy, 0.8f), -51.2f);

    unsigned off[PPT][4];   // byte offsets of the 4 corner pixels
    float    w  [PPT][4];
    bool any = false;

    #pragma unroll
    for (int p = 0; p < PPT; p++) {
        const float pz = __fadd_rn(__fmul_rn((float)(iz0 + p), 0.5f), -5.0f);

        // q = bda @ [px,py,pz,1]
        const float q0 = s_bda[ 0]*px + s_bda[ 1]*py + s_bda[ 2]*pz + s_bda[ 3];
        const float q1 = s_bda[ 4]*px + s_bda[ 5]*py + s_bda[ 6]*pz + s_bda[ 7];
        const float q2 = s_bda[ 8]*px + s_bda[ 9]*py + s_bda[10]*pz + s_bda[11];
        const float q3 = s_bda[12]*px + s_bda[13]*py + s_bda[14]*pz + s_bda[15];

        // pix = proj(3x4) @ q
        const float p0 = s_proj[0]*q0 + s_proj[1]*q1 + s_proj[ 2]*q2 + s_proj[ 3]*q3;
        const float p1 = s_proj[4]*q0 + s_proj[5]*q1 + s_proj[ 6]*q2 + s_proj[ 7]*q3;
        const float p2 = s_proj[8]*q0 + s_proj[9]*q1 + s_proj[10]*q2 + s_proj[11]*q3;

        const float u = __fdiv_rn(p0, p2);
        const float v = __fdiv_rn(p1, p2);

        // un = u/W*2-1 ; x = (un+1)*0.5*(W-1)   (replicate reference op order)
        const float un = __fadd_rn(__fmul_rn(__fdiv_rn(u, 88.0f), 2.0f), -1.0f);
        const float vn = __fadd_rn(__fmul_rn(__fdiv_rn(v, 32.0f), 2.0f), -1.0f);
        float x = __fmul_rn(__fmul_rn(__fadd_rn(un, 1.0f), 0.5f), 87.0f);
        float y = __fmul_rn(__fmul_rn(__fadd_rn(vn, 1.0f), 0.5f), 31.0f);

        // finite check via exponent bits (robust under any fast-math setting)
        const unsigned exb = __float_as_uint(x) & 0x7f800000u;
        const unsigned eyb = __float_as_uint(y) & 0x7f800000u;
        if (exb == 0x7f800000u || eyb == 0x7f800000u) { x = -10.0f; y = -10.0f; }

        const float x0f = floorf(x), y0f = floorf(y);
        const float x1f = x0f + 1.0f, y1f = y0f + 1.0f;
        const float wx1 = x - x0f, wx0 = 1.0f - wx1;
        const float wy1 = y - y0f, wy0 = 1.0f - wy1;

        const bool vx0 = (x0f >= 0.0f) && (x0f < 88.0f);
        const bool vx1 = (x1f >= 0.0f) && (x1f < 88.0f);
        const bool vy0 = (y0f >= 0.0f) && (y0f < 32.0f);
        const bool vy1 = (y1f >= 0.0f) && (y1f < 32.0f);

        const int ix0 = (int)fminf(fmaxf(x0f, 0.0f), 87.0f);
        const int ix1 = (int)fminf(fmaxf(x1f, 0.0f), 87.0f);
        const int iy0 = (int)fminf(fmaxf(y0f, 0.0f), 31.0f);
        const int iy1 = (int)fminf(fmaxf(y1f, 0.0f), 31.0f);

        // byte offsets into channel-last fp16 rows (C_*2 = 160 B per pixel)
        off[p][0] = (unsigned)(iy0 * W_ + ix0) * (C_ * 2);
        off[p][1] = (unsigned)(iy0 * W_ + ix1) * (C_ * 2);
        off[p][2] = (unsigned)(iy1 * W_ + ix0) * (C_ * 2);
        off[p][3] = (unsigned)(iy1 * W_ + ix1) * (C_ * 2);

        w[p][0] = (vx0 && vy0) ? wx0 * wy0 : 0.0f;
        w[p][1] = (vx1 && vy0) ? wx1 * wy0 : 0.0f;
        w[p][2] = (vx0 && vy1) ? wx0 * wy1 : 0.0f;
        w[p][3] = (vx1 && vy1) ? wx1 * wy1 : 0.0f;

        any = any || ((vx0 || vx1) && (vy0 || vy1));
    }

    float2* ob = (float2*)(out + (size_t)b * C_ * NPTS + n0);
    const int stride2 = NPTS / 2;   // float2 stride between channels

    if (!any) {
        const float2 z = make_float2(0.0f, 0.0f);
        #pragma unroll
        for (int c = 0; c < C_; c++)
            __stcs(ob + c * stride2, z);
        return;
    }

    const char* rowbase = (const char*)(g_imgH + (size_t)b * HW_ * C_);

    #pragma unroll 2
    for (int ch = 0; ch < NCH8; ch++) {
        const unsigned chb = ch * 16;
        // front-batch all 8 corner loads (MLP=8)
        float4 ra0 = __ldg((const float4*)(rowbase + off[0][0] + chb));
        float4 rb0 = __ldg((const float4*)(rowbase + off[0][1] + chb));
        float4 rc0 = __ldg((const float4*)(rowbase + off[0][2] + chb));
        float4 rd0 = __ldg((const float4*)(rowbase + off[0][3] + chb));
        float4 ra1 = __ldg((const float4*)(rowbase + off[1][0] + chb));
        float4 rb1 = __ldg((const float4*)(rowbase + off[1][1] + chb));
        float4 rc1 = __ldg((const float4*)(rowbase + off[1][2] + chb));
        float4 rd1 = __ldg((const float4*)(rowbase + off[1][3] + chb));

        const __half2* ha0 = (const __half2*)&ra0;
        const __half2* hb0 = (const __half2*)&rb0;
        const __half2* hc0 = (const __half2*)&rc0;
        const __half2* hd0 = (const __half2*)&rd0;
        const __half2* ha1 = (const __half2*)&ra1;
        const __half2* hb1 = (const __half2*)&rb1;
        const __half2* hc1 = (const __half2*)&rc1;
        const __half2* hd1 = (const __half2*)&rd1;

        float2* o = ob + (ch * 8) * stride2;
        #pragma unroll
        for (int k = 0; k < 4; k++) {
            // point 0, channels 2k / 2k+1
            const float2 fa0 = __half22float2(ha0[k]);
            const float2 fb0 = __half22float2(hb0[k]);
            const float2 fc0 = __half22float2(hc0[k]);
            const float2 fd0 = __half22float2(hd0[k]);
            // point 1
            const float2 fa1 = __half22float2(ha1[k]);
            const float2 fb1 = __half22float2(hb1[k]);
            const float2 fc1 = __half22float2(hc1[k]);
            const float2 fd1 = __half22float2(hd1[k]);

            float2 s0, s1;
            s0.x = w[0][0]*fa0.x + w[0][1]*fb0.x + w[0][2]*fc0.x + w[0][3]*fd0.x;
            s0.y = w[1][0]*fa1.x + w[1][1]*fb1.x + w[1][2]*fc1.x + w[1][3]*fd1.x;
            s1.x = w[0][0]*fa0.y + w[0][1]*fb0.y + w[0][2]*fc0.y + w[0][3]*fd0.y;
            s1.y = w[1][0]*fa1.y + w[1][1]*fb1.y + w[1][2]*fc1.y + w[1][3]*fd1.y;

            __stcs(o + (2 * k)     * stride2, s0);
            __stcs(o + (2 * k + 1) * stride2, s1);
        }
    }
}

extern "C" void kernel_launch(void* const* d_in, const int* in_sizes, int n_in,
                              void* d_out, int out_size)
{
    (void)in_sizes; (void)n_in; (void)out_size;
    const float* img    = (const float*)d_in[0];
    const float* intrin = (const float*)d_in[1];
    const float* extrin = (const float*)d_in[2];
    const float* bda    = (const float*)d_in[3];
    float* out          = (float*)d_out;

    dim3 tgrid((HW_ + 31) / 32, (C_ + 31) / 32, 2);
    fvt_transpose<<<tgrid, dim3(32, 8)>>>(img);

    dim3 grid(NPTS / (TPB * PPT), 2);   // 512 blocks/batch, B=2
    fvt_kernel<<<grid, TPB>>>(intrin, extrin, bda, out);
}

// round 13
// speedup vs baseline: 1.0037x; 1.0037x over previous
#include <cuda_runtime.h>
#include <cuda_fp16.h>
#include <cstdint>

#define C_    80
#define H_    32
#define W_    88
#define HW_   (H_ * W_)          // 2816
#define NXg   128
#define NYg   128
#define NZg   16
#define NPTS  (NXg * NYg * NZg)  // 262144 points per batch
#define TPB   256
#define PPT   2                  // z-adjacent points per thread (STG.64 stores)
#define NCH8  (C_ / 8)           // 10 chunks of 8 fp16 channels (16 B)

// (B, H*W, C) channel-last fp16 copy of the feature map. 900 KB total.
__device__ __half g_imgH[2 * HW_ * C_];

// ---------------------------------------------------------------------------
// Pass 1: (B, C, HW) f32 -> (B, HW, C) fp16 tiled transpose (L2-resident)
// ---------------------------------------------------------------------------
__global__ void fvt_transpose(const float* __restrict__ img)
{
    __shared__ float tile[32][33];
    const int b   = blockIdx.z;
    const int hw0 = blockIdx.x * 32;
    const int c0  = blockIdx.y * 32;
    const int tx  = threadIdx.x;      // 0..31
    const int ty  = threadIdx.y;      // 0..7

    #pragma unroll
    for (int i = 0; i < 4; i++) {
        const int c  = c0 + ty + i * 8;
        const int hw = hw0 + tx;
        if (c < C_ && hw < HW_)
            tile[ty + i * 8][tx] = img[((size_t)b * C_ + c) * HW_ + hw];
    }
    __syncthreads();
    #pragma unroll
    for (int i = 0; i < 4; i++) {
        const int hw = hw0 + ty + i * 8;
        const int c  = c0 + tx;
        if (hw < HW_ && c < C_)
            g_imgH[((size_t)b * HW_ + hw) * C_ + c] =
                __float2half_rn(tile[tx][ty + i * 8]);
    }
}

// ---------------------------------------------------------------------------
// Pass 2: 2 z-adjacent points per thread. fp16 channel-last gathers
// (8 ch per LDG.128), f32 interpolation, STG.64 streamed stores.
// ---------------------------------------------------------------------------
__global__ __launch_bounds__(TPB, 5) void fvt_kernel(
    const float* __restrict__ intrin,  // (B, 1, 4, 4)
    const float* __restrict__ extrin,  // (B, 1, 4, 4)
    const float* __restrict__ bda,     // (B, 4, 4)
    float* __restrict__ out)           // (B, C, NX, NY, NZ)
{
    __shared__ float s_bda[16];
    __shared__ float s_proj[12];

    const int b = blockIdx.y;

    if (threadIdx.x < 16) s_bda[threadIdx.x] = bda[b * 16 + threadIdx.x];
    if (threadIdx.x < 12) {
        // proj[i][j] = sum_k (intrin[i][k] * scale_i) * extrin[k][j]
        const int i = threadIdx.x >> 2;
        const int j = threadIdx.x & 3;
        const float sc = (i < 2) ? 0.125f : 1.0f;
        const float* IN = intrin + b * 16;
        const float* EX = extrin + b * 16;
        float acc = 0.0f;
        #pragma unroll
        for (int k = 0; k < 3; k++)
            acc += (IN[i * 4 + k] * sc) * EX[k * 4 + j];
        s_proj[threadIdx.x] = acc;
    }
    __syncthreads();

    const int n0  = (blockIdx.x * TPB + threadIdx.x) * PPT;
    const int iz0 = n0 & (NZg - 1);         // PPT=2 divides 16: column-local
    const int t   = n0 >> 4;
    const int iy  = t & (NYg - 1);
    const int ix  = t >> 7;

    // match jnp: bound[0] + arange*step  (mul then add, no FMA contraction)
    const float px = __fadd_rn(__fmul_rn((float)ix, 0.8f), -51.2f);
    const float py = __fadd_rn(__fmul_rn((float)iy, 0.8f), -51.2f);

    unsigned off[PPT][4];   // byte offsets of the 4 corner pixels
    float    w  [PPT][4];
    bool any = false;

    #pragma unroll
    for (int p = 0; p < PPT; p++) {
        const float pz = __fadd_rn(__fmul_rn((float)(iz0 + p), 0.5f), -5.0f);

        // q = bda @ [px,py,pz,1]
        const float q0 = s_bda[ 0]*px + s_bda[ 1]*py + s_bda[ 2]*pz + s_bda[ 3];
        const float q1 = s_bda[ 4]*px + s_bda[ 5]*py + s_bda[ 6]*pz + s_bda[ 7];
        const float q2 = s_bda[ 8]*px + s_bda[ 9]*py + s_bda[10]*pz + s_bda[11];
        const float q3 = s_bda[12]*px + s_bda[13]*py + s_bda[14]*pz + s_bda[15];

        // pix = proj(3x4) @ q
        const float p0 = s_proj[0]*q0 + s_proj[1]*q1 + s_proj[ 2]*q2 + s_proj[ 3]*q3;
        const float p1 = s_proj[4]*q0 + s_proj[5]*q1 + s_proj[ 6]*q2 + s_proj[ 7]*q3;
        const float p2 = s_proj[8]*q0 + s_proj[9]*q1 + s_proj[10]*q2 + s_proj[11]*q3;

        const float u = __fdiv_rn(p0, p2);
        const float v = __fdiv_rn(p1, p2);

        // un = u/W*2-1 ; x = (un+1)*0.5*(W-1)   (replicate reference op order)
        const float un = __fadd_rn(__fmul_rn(__fdiv_rn(u, 88.0f), 2.0f), -1.0f);
        const float vn = __fadd_rn(__fmul_rn(__fdiv_rn(v, 32.0f), 2.0f), -1.0f);
        float x = __fmul_rn(__fmul_rn(__fadd_rn(un, 1.0f), 0.5f), 87.0f);
        float y = __fmul_rn(__fmul_rn(__fadd_rn(vn, 1.0f), 0.5f), 31.0f);

        // finite check via exponent bits (robust under any fast-math setting)
        const unsigned exb = __float_as_uint(x) & 0x7f800000u;
        const unsigned eyb = __float_as_uint(y) & 0x7f800000u;
        if (exb == 0x7f800000u || eyb == 0x7f800000u) { x = -10.0f; y = -10.0f; }

        const float x0f = floorf(x), y0f = floorf(y);
        const float x1f = x0f + 1.0f, y1f = y0f + 1.0f;
        const float wx1 = x - x0f, wx0 = 1.0f - wx1;
        const float wy1 = y - y0f, wy0 = 1.0f - wy1;

        const bool vx0 = (x0f >= 0.0f) && (x0f < 88.0f);
        const bool vx1 = (x1f >= 0.0f) && (x1f < 88.0f);
        const bool vy0 = (y0f >= 0.0f) && (y0f < 32.0f);
        const bool vy1 = (y1f >= 0.0f) && (y1f < 32.0f);

        const int ix0 = (int)fminf(fmaxf(x0f, 0.0f), 87.0f);
        const int ix1 = (int)fminf(fmaxf(x1f, 0.0f), 87.0f);
        const int iy0 = (int)fminf(fmaxf(y0f, 0.0f), 31.0f);
        const int iy1 = (int)fminf(fmaxf(y1f, 0.0f), 31.0f);

        // byte offsets into channel-last fp16 rows (C_*2 = 160 B per pixel)
        off[p][0] = (unsigned)(iy0 * W_ + ix0) * (C_ * 2);
        off[p][1] = (unsigned)(iy0 * W_ + ix1) * (C_ * 2);
        off[p][2] = (unsigned)(iy1 * W_ + ix0) * (C_ * 2);
        off[p][3] = (unsigned)(iy1 * W_ + ix1) * (C_ * 2);

        w[p][0] = (vx0 && vy0) ? wx0 * wy0 : 0.0f;
        w[p][1] = (vx1 && vy0) ? wx1 * wy0 : 0.0f;
        w[p][2] = (vx0 && vy1) ? wx0 * wy1 : 0.0f;
        w[p][3] = (vx1 && vy1) ? wx1 * wy1 : 0.0f;

        any = any || ((vx0 || vx1) && (vy0 || vy1));
    }

    float2* ob = (float2*)(out + (size_t)b * C_ * NPTS + n0);
    const int stride2 = NPTS / 2;   // float2 stride between channels

    if (!any) {
        const float2 z = make_float2(0.0f, 0.0f);
        #pragma unroll
        for (int c = 0; c < C_; c++)
            __stcs(ob + c * stride2, z);
        return;
    }

    const char* rowbase = (const char*)(g_imgH + (size_t)b * HW_ * C_);

    #pragma unroll 2
    for (int ch = 0; ch < NCH8; ch++) {
        const unsigned chb = ch * 16;
        // front-batch all 8 corner loads (MLP=8)
        float4 ra0 = __ldg((const float4*)(rowbase + off[0][0] + chb));
        float4 rb0 = __ldg((const float4*)(rowbase + off[0][1] + chb));
        float4 rc0 = __ldg((const float4*)(rowbase + off[0][2] + chb));
        float4 rd0 = __ldg((const float4*)(rowbase + off[0][3] + chb));
        float4 ra1 = __ldg((const float4*)(rowbase + off[1][0] + chb));
        float4 rb1 = __ldg((const float4*)(rowbase + off[1][1] + chb));
        float4 rc1 = __ldg((const float4*)(rowbase + off[1][2] + chb));
        float4 rd1 = __ldg((const float4*)(rowbase + off[1][3] + chb));

        const __half2* ha0 = (const __half2*)&ra0;
        const __half2* hb0 = (const __half2*)&rb0;
        const __half2* hc0 = (const __half2*)&rc0;
        const __half2* hd0 = (const __half2*)&rd0;
        const __half2* ha1 = (const __half2*)&ra1;
        const __half2* hb1 = (const __half2*)&rb1;
        const __half2* hc1 = (const __half2*)&rc1;
        const __half2* hd1 = (const __half2*)&rd1;

        float2* o = ob + (ch * 8) * stride2;
        #pragma unroll
        for (int k = 0; k < 4; k++) {
            // point 0, channels 2k / 2k+1
            const float2 fa0 = __half22float2(ha0[k]);
            const float2 fb0 = __half22float2(hb0[k]);
            const float2 fc0 = __half22float2(hc0[k]);
            const float2 fd0 = __half22float2(hd0[k]);
            // point 1
            const float2 fa1 = __half22float2(ha1[k]);
            const float2 fb1 = __half22float2(hb1[k]);
            const float2 fc1 = __half22float2(hc1[k]);
            const float2 fd1 = __half22float2(hd1[k]);

            float2 s0, s1;
            s0.x = w[0][0]*fa0.x + w[0][1]*fb0.x + w[0][2]*fc0.x + w[0][3]*fd0.x;
            s0.y = w[1][0]*fa1.x + w[1][1]*fb1.x + w[1][2]*fc1.x + w[1][3]*fd1.x;
            s1.x = w[0][0]*fa0.y + w[0][1]*fb0.y + w[0][2]*fc0.y + w[0][3]*fd0.y;
            s1.y = w[1][0]*fa1.y + w[1][1]*fb1.y + w[1][2]*fc1.y + w[1][3]*fd1.y;

            __stcs(o + (2 * k)     * stride2, s0);
            __stcs(o + (2 * k + 1) * stride2, s1);
        }
    }
}

extern "C" void kernel_launch(void* const* d_in, const int* in_sizes, int n_in,
                              void* d_out, int out_size)
{
    (void)in_sizes; (void)n_in; (void)out_size;
    const float* img    = (const float*)d_in[0];
    const float* intrin = (const float*)d_in[1];
    const float* extrin = (const float*)d_in[2];
    const float* bda    = (const float*)d_in[3];
    float* out          = (float*)d_out;

    dim3 tgrid((HW_ + 31) / 32, (C_ + 31) / 32, 2);
    fvt_transpose<<<tgrid, dim3(32, 8)>>>(img);

    dim3 grid(NPTS / (TPB * PPT), 2);   // 512 blocks/batch, B=2
    fvt_kernel<<<grid, TPB>>>(intrin, extrin, bda, out);
}